// round 1
// baseline (speedup 1.0000x reference)
#include <cuda_runtime.h>

// ---------------------------------------------------------------------------
// SuperPointMatching_OT: threshold-search + ordered nonzero extraction.
//
// inner[i,j] = exp(ms[i,j]) * ref[i] * src[j]   (i,j in [0,8192); ms stride 8193)
// thres = first t in {0.5, 0.5-0.01f, ...} with count(inner > t) >= 2048
// outputs (24576 fp32): ref_idx[8192] | src_idx[8192] | scores[8192]
//   slot p < count: p-th nonzero in row-major order; else (-1, -1, 0).
// ---------------------------------------------------------------------------

#define NROWS    8192u
#define STRIDE   8193u
#define TOTAL    (8192u * 8192u)
#define KCORR    2048u
#define MAXCORR  8192
#define NTHRES   64
#define K_SPEC   45          // speculative collection cutoff bucket (T[45] ~ 0.05)
#define LOGCUT   (-3.0f)     // exp(-3)=0.0498 < T[45] and ref*src < 1 => safe reject
#define CAP      (4u * 1024u * 1024u)
#define FCAP     65536u
#define BUFCAP   3072u

__device__ unsigned dHist[NTHRES];
__device__ float    dThres;
__device__ unsigned dCount;
__device__ unsigned dDeep;        // need full-depth histogram pass
__device__ unsigned dRecollect;   // need re-collection pass
__device__ unsigned dCollected;
__device__ unsigned dNF;
__device__ unsigned dCandIdx[CAP];
__device__ float    dCandVal[CAP];
__device__ unsigned dFIdx[FCAP];
__device__ float    dFVal[FCAP];

// Threshold table built exactly like the reference loop: fp32 iterative subtract.
__device__ __forceinline__ void build_table(float* T) {
    float t = 0.5f;
#pragma unroll
    for (int k = 0; k < NTHRES; k++) { T[k] = t; t = t - 0.01f; }
}

// Smallest k in [0, kmax] with v > T[k]. Caller guarantees v > T[kmax] is
// reachable (main: v > T[K_SPEC]; fb: v >= 0 > T[52..]). Estimate +- small scan.
__device__ __forceinline__ int find_bucket(float v, const float* T, int kmax) {
    int k = (int)((0.5f - v) * 100.0f) - 2;
    k = k < 0 ? 0 : (k > kmax ? kmax : k);
    while (k > 0 && v > T[k - 1]) k--;
    while (k < kmax && !(v > T[k])) k++;
    return k;
}

// ---------------------------------------------------------------------------
__global__ void k_init(float* out, int out_size) {
    unsigned i = blockIdx.x * blockDim.x + threadIdx.x;
    if (i < NTHRES) dHist[i] = 0u;
    if (i == 0) {
        dCollected = 0u; dNF = 0u; dDeep = 0u; dRecollect = 0u;
        dCount = 0u; dThres = 0.0f;
    }
    unsigned step = gridDim.x * blockDim.x;
    for (unsigned j = i; j < (unsigned)out_size; j += step)
        out[j] = (j < 2u * MAXCORR) ? -1.0f : 0.0f;
}

// ---------------------------------------------------------------------------
// Main fused pass: fine histogram for buckets <= K_SPEC + speculative collect.
__global__ void __launch_bounds__(256) k_main(const float* __restrict__ ms,
                                              const float* __restrict__ refw,
                                              const float* __restrict__ srcw) {
    __shared__ float    T[NTHRES];
    __shared__ unsigned sHist[NTHRES];
    __shared__ unsigned sN, sBase;
    __shared__ unsigned sIdx[BUFCAP];
    __shared__ float    sVal[BUFCAP];

    const unsigned tid = threadIdx.x;
    if (tid == 0) { build_table(T); sN = 0u; }
    if (tid < NTHRES) sHist[tid] = 0u;
    __syncthreads();

    const float tspec = T[K_SPEC];
    const unsigned step = gridDim.x * blockDim.x;
    const unsigned t0 = blockIdx.x * blockDim.x + tid;

    for (unsigned base = t0; base < TOTAL; base += 4u * step) {
        float m[4]; unsigned id[4]; bool ok[4];
#pragma unroll
        for (int u = 0; u < 4; u++) {
            id[u] = base + (unsigned)u * step;
            ok[u] = id[u] < TOTAL;
            unsigned off = (id[u] >> 13) * STRIDE + (id[u] & 8191u);
            m[u] = ok[u] ? __ldcs(ms + off) : -1e30f;
        }
#pragma unroll
        for (int u = 0; u < 4; u++) {
            if (ok[u] && m[u] > LOGCUT) {
                unsigned i = id[u] >> 13, j = id[u] & 8191u;
                float w = __fmul_rn(refw[i], srcw[j]);
                float v = __fmul_rn(expf(m[u]), w);
                if (v > tspec) {
                    int k = find_bucket(v, T, K_SPEC);
                    atomicAdd(&sHist[k], 1u);
                    unsigned p = atomicAdd(&sN, 1u);
                    if (p < BUFCAP) { sIdx[p] = id[u]; sVal[p] = v; }
                    else {
                        unsigned g = atomicAdd(&dCollected, 1u);
                        if (g < CAP) { dCandIdx[g] = id[u]; dCandVal[g] = v; }
                    }
                }
            }
        }
    }

    __syncthreads();
    if (tid < NTHRES && sHist[tid]) atomicAdd(&dHist[tid], sHist[tid]);
    if (tid == 0) {
        unsigned n = sN < BUFCAP ? sN : BUFCAP;
        sBase = atomicAdd(&dCollected, n);
    }
    __syncthreads();
    unsigned n = sN < BUFCAP ? sN : BUFCAP;
    for (unsigned p = tid; p < n; p += blockDim.x) {
        unsigned g = sBase + p;
        if (g < CAP) { dCandIdx[g] = sIdx[p]; dCandVal[g] = sVal[p]; }
    }
}

// ---------------------------------------------------------------------------
__global__ void k_thres() {
    float T[NTHRES];
    build_table(T);
    unsigned cum = 0; int ks = -1;
    for (int k = 0; k <= K_SPEC; k++) {
        cum += dHist[k];
        if (cum >= KCORR) { ks = k; break; }
    }
    if (ks < 0) {                 // threshold below T[K_SPEC]: need deep pass
        dDeep = 1u; dRecollect = 1u; dCollected = 0u;
    } else {
        dThres = T[ks]; dCount = cum;
        if (dCollected > CAP) { dRecollect = 1u; dCollected = 0u; }
    }
}

// ---------------------------------------------------------------------------
// Fallback: full-depth histogram for buckets > K_SPEC (rare path).
__global__ void __launch_bounds__(256) k_fb_hist(const float* __restrict__ ms,
                                                 const float* __restrict__ refw,
                                                 const float* __restrict__ srcw) {
    if (dDeep == 0u) return;
    __shared__ unsigned short h[8][NTHRES][32];   // per-(warp,lane) counters
    __shared__ float T[NTHRES];
    const unsigned tid = threadIdx.x;
    if (tid == 0) build_table(T);
    {
        unsigned* hz = (unsigned*)h;
        for (unsigned p = tid; p < 8u * NTHRES * 32u / 2u; p += blockDim.x) hz[p] = 0u;
    }
    __syncthreads();

    const float tspec = T[K_SPEC];
    const unsigned wrp = tid >> 5, lane = tid & 31u;
    const unsigned step = gridDim.x * blockDim.x;
    for (unsigned idx = blockIdx.x * blockDim.x + tid; idx < TOTAL; idx += step) {
        unsigned i = idx >> 13, j = idx & 8191u;
        float m = __ldg(ms + i * STRIDE + j);
        float w = __fmul_rn(refw[i], srcw[j]);
        float v = __fmul_rn(expf(m), w);
        if (!(v > tspec)) {                      // buckets <= K_SPEC already counted
            int k = find_bucket(v, T, NTHRES - 1);
            h[wrp][k][lane]++;
        }
    }
    __syncthreads();
    if (tid < NTHRES) {
        unsigned s = 0;
        for (int wq = 0; wq < 8; wq++)
            for (int l = 0; l < 32; l++) s += h[wq][tid][l];
        if (s) atomicAdd(&dHist[tid], s);
    }
}

__global__ void k_thres2() {
    if (dDeep == 0u) return;
    float T[NTHRES];
    build_table(T);
    unsigned cum = 0; int ks = NTHRES - 1;
    for (int k = 0; k < NTHRES; k++) {
        cum += dHist[k];
        if (cum >= KCORR) { ks = k; break; }
    }
    dThres = T[ks]; dCount = cum;
}

// ---------------------------------------------------------------------------
// Re-collection with the final threshold (rare path).
__global__ void __launch_bounds__(256) k_collect2(const float* __restrict__ ms,
                                                  const float* __restrict__ refw,
                                                  const float* __restrict__ srcw) {
    if (dRecollect == 0u) return;
    __shared__ unsigned sN, sBase;
    __shared__ unsigned sIdx[BUFCAP];
    __shared__ float    sVal[BUFCAP];
    const unsigned tid = threadIdx.x;
    if (tid == 0) sN = 0u;
    __syncthreads();

    const float th = dThres;
    float lcut = -1e30f;
    if (th > 1e-30f) lcut = __logf(th) - 0.02f;   // conservative reject
    const unsigned step = gridDim.x * blockDim.x;
    for (unsigned idx = blockIdx.x * blockDim.x + tid; idx < TOTAL; idx += step) {
        unsigned i = idx >> 13, j = idx & 8191u;
        float m = __ldg(ms + i * STRIDE + j);
        if (m > lcut) {
            float w = __fmul_rn(refw[i], srcw[j]);
            float v = __fmul_rn(expf(m), w);
            if (v > th) {
                unsigned p = atomicAdd(&sN, 1u);
                if (p < BUFCAP) { sIdx[p] = idx; sVal[p] = v; }
                else {
                    unsigned g = atomicAdd(&dCollected, 1u);
                    if (g < CAP) { dCandIdx[g] = idx; dCandVal[g] = v; }
                }
            }
        }
    }
    __syncthreads();
    if (tid == 0) {
        unsigned n = sN < BUFCAP ? sN : BUFCAP;
        sBase = atomicAdd(&dCollected, n);
    }
    __syncthreads();
    unsigned n = sN < BUFCAP ? sN : BUFCAP;
    for (unsigned p = tid; p < n; p += blockDim.x) {
        unsigned g = sBase + p;
        if (g < CAP) { dCandIdx[g] = sIdx[p]; dCandVal[g] = sVal[p]; }
    }
}

// ---------------------------------------------------------------------------
// Compact candidates that pass the final threshold.
__global__ void k_compact() {
    unsigned n = dCollected < CAP ? dCollected : CAP;
    unsigned step = gridDim.x * blockDim.x;
    float th = dThres;
    for (unsigned i = blockIdx.x * blockDim.x + threadIdx.x; i < n; i += step) {
        float v = dCandVal[i];
        if (v > th) {
            unsigned p = atomicAdd(&dNF, 1u);
            if (p < FCAP) { dFIdx[p] = dCandIdx[i]; dFVal[p] = v; }
        }
    }
}

// ---------------------------------------------------------------------------
// Rank-based ordered write: slot = #{candidates with smaller linear index}.
__global__ void k_rank(float* out) {
    __shared__ unsigned sBuf[4096];
    unsigned n = dNF < FCAP ? dNF : FCAP;
    if (blockIdx.x * blockDim.x >= n) return;   // uniform per block

    unsigned i = blockIdx.x * blockDim.x + threadIdx.x;
    unsigned Li = (i < n) ? dFIdx[i] : 0xFFFFFFFFu;
    float    Vi = (i < n) ? dFVal[i] : 0.0f;
    unsigned rank = 0;
    for (unsigned base = 0; base < n; base += 4096u) {
        unsigned m = n - base; if (m > 4096u) m = 4096u;
        __syncthreads();
        for (unsigned p = threadIdx.x; p < m; p += blockDim.x) sBuf[p] = dFIdx[base + p];
        __syncthreads();
        if (i < n)
            for (unsigned p = 0; p < m; p++) rank += (sBuf[p] < Li) ? 1u : 0u;
    }
    if (i < n && rank < (unsigned)MAXCORR) {
        unsigned r = Li >> 13, c = Li & 8191u;
        out[rank]               = (float)r;
        out[MAXCORR + rank]     = (float)c;
        out[2 * MAXCORR + rank] = Vi;
    }
}

// ---------------------------------------------------------------------------
extern "C" void kernel_launch(void* const* d_in, const int* in_sizes, int n_in,
                              void* d_out, int out_size) {
    const float* ms   = (const float*)d_in[0];   // (8193, 8193) f32
    const float* refw = (const float*)d_in[1];   // (8192,) f32
    const float* srcw = (const float*)d_in[2];   // (8192,) f32
    float* out = (float*)d_out;                  // 24576 f32

    k_init<<<96, 256>>>(out, out_size);
    k_main<<<2048, 256>>>(ms, refw, srcw);
    k_thres<<<1, 1>>>();
    k_fb_hist<<<2048, 256>>>(ms, refw, srcw);    // no-op unless dDeep
    k_thres2<<<1, 1>>>();                        // no-op unless dDeep
    k_collect2<<<2048, 256>>>(ms, refw, srcw);   // no-op unless dRecollect
    k_compact<<<256, 256>>>();
    k_rank<<<256, 256>>>(out);
}

// round 2
// speedup vs baseline: 1.0471x; 1.0471x over previous
#include <cuda_runtime.h>

// ---------------------------------------------------------------------------
// SuperPointMatching_OT: threshold-search + ordered nonzero extraction.
//
// inner[i,j] = exp(ms[i,j]) * ref[i] * src[j]   (i,j in [0,8192); ms stride 8193)
// thres = first t in {0.5, 0.5-0.01f, ...} with count(inner > t) >= 2048
// outputs (24576 fp32): ref_idx[8192] | src_idx[8192] | scores[8192]
// ---------------------------------------------------------------------------

#define STRIDE   8193u
#define NELEM    (8193u * 8193u)          // 67,125,249 (last elem = dustbin corner)
#define NVEC     (NELEM / 4u)             // 16,781,312 float4s; tail = corner only
#define TOTAL    (8192u * 8192u)
#define KCORR    2048u
#define MAXCORR  8192
#define NTHRES   64
#define K_SPEC   45          // speculative collection cutoff bucket (T[45] ~ 0.05)
#define LOGCUT   (-3.0f)     // exp(-3)=0.0498 < T[45]; ref*src < 1 => safe reject
#define CAP      (4u * 1024u * 1024u)
#define FCAP     65536u
#define BUFCAP   3072u

__device__ unsigned dHist[NTHRES];
__device__ float    dThres;
__device__ unsigned dCount;
__device__ unsigned dDeep;        // need full-depth histogram pass
__device__ unsigned dRecollect;   // need re-collection pass
__device__ unsigned dCollected;
__device__ unsigned dNF;
__device__ unsigned dCandIdx[CAP];
__device__ float    dCandVal[CAP];
__device__ unsigned dFIdx[FCAP];
__device__ float    dFVal[FCAP];

// Threshold table built exactly like the reference loop: fp32 iterative subtract.
__device__ __forceinline__ void build_table(float* T) {
    float t = 0.5f;
#pragma unroll
    for (int k = 0; k < NTHRES; k++) { T[k] = t; t = t - 0.01f; }
}

// Smallest k in [0, kmax] with v > T[k].
__device__ __forceinline__ int find_bucket(float v, const float* T, int kmax) {
    int k = (int)((0.5f - v) * 100.0f) - 2;
    k = k < 0 ? 0 : (k > kmax ? kmax : k);
    while (k > 0 && v > T[k - 1]) k--;
    while (k < kmax && !(v > T[k])) k++;
    return k;
}

// ---------------------------------------------------------------------------
__global__ void k_init(float* out, int out_size) {
    unsigned i = blockIdx.x * blockDim.x + threadIdx.x;
    if (i < NTHRES) dHist[i] = 0u;
    if (i == 0) {
        dCollected = 0u; dNF = 0u; dDeep = 0u; dRecollect = 0u;
        dCount = 0u; dThres = 0.0f;
    }
    unsigned step = gridDim.x * blockDim.x;
    for (unsigned j = i; j < (unsigned)out_size; j += step)
        out[j] = (j < 2u * MAXCORR) ? -1.0f : 0.0f;
}

// ---------------------------------------------------------------------------
// Rare-path handler: full evaluation of one element at linear position p.
__device__ __forceinline__ void handle_elem(
    unsigned p, float m, const float* __restrict__ refw,
    const float* __restrict__ srcw, const float* T, float tspec,
    unsigned* sHist, unsigned* sN, unsigned* sIdx, float* sVal)
{
    unsigned i = p / STRIDE;
    unsigned j = p - i * STRIDE;
    if (i >= 8192u || j >= 8192u) return;        // dustbin row/col
    float w = __fmul_rn(refw[i], srcw[j]);
    float v = __fmul_rn(expf(m), w);
    if (v > tspec) {
        int k = find_bucket(v, T, K_SPEC);
        atomicAdd(&sHist[k], 1u);
        unsigned pp = atomicAdd(sN, 1u);
        unsigned id = (i << 13) | j;
        if (pp < BUFCAP) { sIdx[pp] = id; sVal[pp] = v; }
        else {
            unsigned g = atomicAdd(&dCollected, 1u);
            if (g < CAP) { dCandIdx[g] = id; dCandVal[g] = v; }
        }
    }
}

// Main fused pass: vectorized stream + fine histogram (<=K_SPEC) + collect.
__global__ void __launch_bounds__(256) k_main(const float4* __restrict__ ms4,
                                              const float* __restrict__ refw,
                                              const float* __restrict__ srcw) {
    __shared__ float    T[NTHRES];
    __shared__ unsigned sHist[NTHRES];
    __shared__ unsigned sN, sBase;
    __shared__ unsigned sIdx[BUFCAP];
    __shared__ float    sVal[BUFCAP];

    const unsigned tid = threadIdx.x;
    if (tid == 0) { build_table(T); sN = 0u; }
    if (tid < NTHRES) sHist[tid] = 0u;
    __syncthreads();

    const float tspec = T[K_SPEC];
    const unsigned step = gridDim.x * blockDim.x;
    const unsigned t0 = blockIdx.x * blockDim.x + tid;

    for (unsigned base = t0; base < NVEC; base += 4u * step) {
        float4 a[4]; unsigned vp[4]; bool ok[4];
#pragma unroll
        for (int u = 0; u < 4; u++) {
            vp[u] = base + (unsigned)u * step;
            ok[u] = vp[u] < NVEC;
            if (ok[u]) a[u] = __ldcs(ms4 + vp[u]);
            else a[u] = make_float4(-1e30f, -1e30f, -1e30f, -1e30f);
        }
#pragma unroll
        for (int u = 0; u < 4; u++) {
            float mx = fmaxf(fmaxf(a[u].x, a[u].y), fmaxf(a[u].z, a[u].w));
            if (mx > LOGCUT) {
                unsigned p0 = vp[u] * 4u;
                if (a[u].x > LOGCUT) handle_elem(p0 + 0u, a[u].x, refw, srcw, T, tspec, sHist, &sN, sIdx, sVal);
                if (a[u].y > LOGCUT) handle_elem(p0 + 1u, a[u].y, refw, srcw, T, tspec, sHist, &sN, sIdx, sVal);
                if (a[u].z > LOGCUT) handle_elem(p0 + 2u, a[u].z, refw, srcw, T, tspec, sHist, &sN, sIdx, sVal);
                if (a[u].w > LOGCUT) handle_elem(p0 + 3u, a[u].w, refw, srcw, T, tspec, sHist, &sN, sIdx, sVal);
            }
        }
    }

    __syncthreads();
    if (tid < NTHRES && sHist[tid]) atomicAdd(&dHist[tid], sHist[tid]);
    if (tid == 0) {
        unsigned n = sN < BUFCAP ? sN : BUFCAP;
        sBase = atomicAdd(&dCollected, n);
    }
    __syncthreads();
    unsigned n = sN < BUFCAP ? sN : BUFCAP;
    for (unsigned p = tid; p < n; p += blockDim.x) {
        unsigned g = sBase + p;
        if (g < CAP) { dCandIdx[g] = sIdx[p]; dCandVal[g] = sVal[p]; }
    }
}

// ---------------------------------------------------------------------------
__global__ void k_thres() {
    float T[NTHRES];
    build_table(T);
    unsigned cum = 0; int ks = -1;
    for (int k = 0; k <= K_SPEC; k++) {
        cum += dHist[k];
        if (cum >= KCORR) { ks = k; break; }
    }
    if (ks < 0) {                 // threshold below T[K_SPEC]: need deep pass
        dDeep = 1u; dRecollect = 1u; dCollected = 0u;
    } else {
        dThres = T[ks]; dCount = cum;
        if (dCollected > CAP) { dRecollect = 1u; dCollected = 0u; }
    }
}

// ---------------------------------------------------------------------------
// Fallback: full-depth histogram for buckets > K_SPEC (rare path).
__global__ void __launch_bounds__(256) k_fb_hist(const float* __restrict__ ms,
                                                 const float* __restrict__ refw,
                                                 const float* __restrict__ srcw) {
    if (dDeep == 0u) return;
    __shared__ unsigned short h[8][NTHRES][32];
    __shared__ float T[NTHRES];
    const unsigned tid = threadIdx.x;
    if (tid == 0) build_table(T);
    {
        unsigned* hz = (unsigned*)h;
        for (unsigned p = tid; p < 8u * NTHRES * 32u / 2u; p += blockDim.x) hz[p] = 0u;
    }
    __syncthreads();

    const float tspec = T[K_SPEC];
    const unsigned wrp = tid >> 5, lane = tid & 31u;
    const unsigned step = gridDim.x * blockDim.x;
    for (unsigned idx = blockIdx.x * blockDim.x + tid; idx < TOTAL; idx += step) {
        unsigned i = idx >> 13, j = idx & 8191u;
        float m = __ldg(ms + i * STRIDE + j);
        float w = __fmul_rn(refw[i], srcw[j]);
        float v = __fmul_rn(expf(m), w);
        if (!(v > tspec)) {
            int k = find_bucket(v, T, NTHRES - 1);
            h[wrp][k][lane]++;
        }
    }
    __syncthreads();
    if (tid < NTHRES) {
        unsigned s = 0;
        for (int wq = 0; wq < 8; wq++)
            for (int l = 0; l < 32; l++) s += h[wq][tid][l];
        if (s) atomicAdd(&dHist[tid], s);
    }
}

__global__ void k_thres2() {
    if (dDeep == 0u) return;
    float T[NTHRES];
    build_table(T);
    unsigned cum = 0; int ks = NTHRES - 1;
    for (int k = 0; k < NTHRES; k++) {
        cum += dHist[k];
        if (cum >= KCORR) { ks = k; break; }
    }
    dThres = T[ks]; dCount = cum;
}

// ---------------------------------------------------------------------------
// Re-collection with the final threshold (rare path).
__global__ void __launch_bounds__(256) k_collect2(const float* __restrict__ ms,
                                                  const float* __restrict__ refw,
                                                  const float* __restrict__ srcw) {
    if (dRecollect == 0u) return;
    __shared__ unsigned sN, sBase;
    __shared__ unsigned sIdx[BUFCAP];
    __shared__ float    sVal[BUFCAP];
    const unsigned tid = threadIdx.x;
    if (tid == 0) sN = 0u;
    __syncthreads();

    const float th = dThres;
    float lcut = -1e30f;
    if (th > 1e-30f) lcut = __logf(th) - 0.02f;
    const unsigned step = gridDim.x * blockDim.x;
    for (unsigned idx = blockIdx.x * blockDim.x + tid; idx < TOTAL; idx += step) {
        unsigned i = idx >> 13, j = idx & 8191u;
        float m = __ldg(ms + i * STRIDE + j);
        if (m > lcut) {
            float w = __fmul_rn(refw[i], srcw[j]);
            float v = __fmul_rn(expf(m), w);
            if (v > th) {
                unsigned p = atomicAdd(&sN, 1u);
                if (p < BUFCAP) { sIdx[p] = idx; sVal[p] = v; }
                else {
                    unsigned g = atomicAdd(&dCollected, 1u);
                    if (g < CAP) { dCandIdx[g] = idx; dCandVal[g] = v; }
                }
            }
        }
    }
    __syncthreads();
    if (tid == 0) {
        unsigned n = sN < BUFCAP ? sN : BUFCAP;
        sBase = atomicAdd(&dCollected, n);
    }
    __syncthreads();
    unsigned n = sN < BUFCAP ? sN : BUFCAP;
    for (unsigned p = tid; p < n; p += blockDim.x) {
        unsigned g = sBase + p;
        if (g < CAP) { dCandIdx[g] = sIdx[p]; dCandVal[g] = sVal[p]; }
    }
}

// ---------------------------------------------------------------------------
// Compact candidates that pass the final threshold.
__global__ void k_compact() {
    unsigned n = dCollected < CAP ? dCollected : CAP;
    unsigned step = gridDim.x * blockDim.x;
    float th = dThres;
    for (unsigned i = blockIdx.x * blockDim.x + threadIdx.x; i < n; i += step) {
        float v = dCandVal[i];
        if (v > th) {
            unsigned p = atomicAdd(&dNF, 1u);
            if (p < FCAP) { dFIdx[p] = dCandIdx[i]; dFVal[p] = v; }
        }
    }
}

// ---------------------------------------------------------------------------
// Rank-based ordered write: slot = #{candidates with smaller linear index}.
__global__ void k_rank(float* out) {
    __shared__ unsigned sBuf[4096];
    unsigned n = dNF < FCAP ? dNF : FCAP;
    if (blockIdx.x * blockDim.x >= n) return;   // uniform per block

    unsigned i = blockIdx.x * blockDim.x + threadIdx.x;
    unsigned Li = (i < n) ? dFIdx[i] : 0xFFFFFFFFu;
    float    Vi = (i < n) ? dFVal[i] : 0.0f;
    unsigned rank = 0;
    for (unsigned base = 0; base < n; base += 4096u) {
        unsigned m = n - base; if (m > 4096u) m = 4096u;
        __syncthreads();
        for (unsigned p = threadIdx.x; p < m; p += blockDim.x) sBuf[p] = dFIdx[base + p];
        __syncthreads();
        if (i < n)
            for (unsigned p = 0; p < m; p++) rank += (sBuf[p] < Li) ? 1u : 0u;
    }
    if (i < n && rank < (unsigned)MAXCORR) {
        unsigned r = Li >> 13, c = Li & 8191u;
        out[rank]               = (float)r;
        out[MAXCORR + rank]     = (float)c;
        out[2 * MAXCORR + rank] = Vi;
    }
}

// ---------------------------------------------------------------------------
extern "C" void kernel_launch(void* const* d_in, const int* in_sizes, int n_in,
                              void* d_out, int out_size) {
    const float* ms   = (const float*)d_in[0];   // (8193, 8193) f32
    const float* refw = (const float*)d_in[1];   // (8192,) f32
    const float* srcw = (const float*)d_in[2];   // (8192,) f32
    float* out = (float*)d_out;                  // 24576 f32

    k_init<<<96, 256>>>(out, out_size);
    k_main<<<2048, 256>>>((const float4*)ms, refw, srcw);
    k_thres<<<1, 1>>>();
    k_fb_hist<<<1024, 256>>>(ms, refw, srcw);    // no-op unless dDeep
    k_thres2<<<1, 1>>>();                        // no-op unless dDeep
    k_collect2<<<1024, 256>>>(ms, refw, srcw);   // no-op unless dRecollect
    k_compact<<<64, 256>>>();
    k_rank<<<256, 256>>>(out);
}